// round 15
// baseline (speedup 1.0000x reference)
#include <cuda_runtime.h>
#include <cuda_bf16.h>
#include <math.h>
#include <stdint.h>

// ---------------------------------------------------------------------------
// Problem constants
// ---------------------------------------------------------------------------
#define NMAX 50000
#define EMAX 800000

// ---------------------------------------------------------------------------
// Scratch (device globals)
// h/rh (gemm->agg gather operands) stay fp32, double-buffered (ping-pong).
// All GEMM A-operands live as pre-split bf16 hi/lo planes.
// ---------------------------------------------------------------------------
__device__ float g_h  [2][(size_t)NMAX * 128];
__device__ float g_rh [2][(size_t)NMAX * 128];
__device__ float g_el [2][(size_t)NMAX * 2];
__device__ float g_er [2][(size_t)NMAX * 2];
__device__ float g_hp [(size_t)NMAX * 64];       // pg h (fp32: pg residual)
__device__ float g_hq [(size_t)NMAX * 64];       // pg Wh (fp32 gather)
__device__ float g_el2[(size_t)NMAX * 2];
__device__ float g_er2[(size_t)NMAX * 2];
__device__ int   g_off[NMAX + 1];
__device__ int   g_cnt[NMAX];
__device__ int   g_esrc[EMAX];

// bf16 hi/lo planes for GEMM A operands
__device__ uint16_t g_fvh [(size_t)NMAX * 128], g_fvl [(size_t)NMAX * 128];
__device__ uint16_t g_poh [(size_t)NMAX * 64],  g_pol [(size_t)NMAX * 64];
__device__ uint16_t g_hsh [(size_t)NMAX * 128], g_hsl [(size_t)NMAX * 128];
__device__ uint16_t g_hs2h[(size_t)NMAX * 128], g_hs2l[(size_t)NMAX * 128];
__device__ uint16_t g_hph [(size_t)NMAX * 64],  g_hpl [(size_t)NMAX * 64];
__device__ uint16_t g_ohph[(size_t)NMAX * 64],  g_ohpl[(size_t)NMAX * 64];

#define WT_FUSED (256 * 192)
#define WT_SMALL (64 * 64)
__device__ uint16_t g_wthi[3 * WT_FUSED + 2 * WT_SMALL];
__device__ uint16_t g_wtlo[3 * WT_FUSED + 2 * WT_SMALL];

// ---------------------------------------------------------------------------
// Helpers
// ---------------------------------------------------------------------------
__device__ __forceinline__ uint32_t smem_u32(const void* p) {
    uint32_t a;
    asm("{ .reg .u64 t; cvta.to.shared.u64 t, %1; cvt.u32.u64 %0, t; }"
        : "=r"(a) : "l"(p));
    return a;
}

__device__ __forceinline__ void ldsm_x4(uint32_t* r, uint32_t addr) {
    asm volatile("ldmatrix.sync.aligned.m8n8.x4.shared.b16 {%0,%1,%2,%3}, [%4];"
                 : "=r"(r[0]), "=r"(r[1]), "=r"(r[2]), "=r"(r[3]) : "r"(addr));
}

__device__ __forceinline__ void mma16816(float* c, const uint32_t* a, const uint32_t* b) {
    asm volatile(
        "mma.sync.aligned.m16n8k16.row.col.f32.bf16.bf16.f32 "
        "{%0,%1,%2,%3}, {%4,%5,%6,%7}, {%8,%9}, {%0,%1,%2,%3};"
        : "+f"(c[0]), "+f"(c[1]), "+f"(c[2]), "+f"(c[3])
        : "r"(a[0]), "r"(a[1]), "r"(a[2]), "r"(a[3]), "r"(b[0]), "r"(b[1]));
}

__device__ __forceinline__ void cpasync16(uint32_t s, const void* g) {
    asm volatile("cp.async.cg.shared.global [%0], [%1], 16;" :: "r"(s), "l"(g));
}
// zero-fill variant: copies pb bytes (0 or 16), rest zero.
__device__ __forceinline__ void cpasync16z(uint32_t s, const void* g, int pb) {
    asm volatile("cp.async.cg.shared.global [%0], [%1], 16, %2;"
                 :: "r"(s), "l"(g), "r"(pb));
}
__device__ __forceinline__ void cpasync_wait() {
    asm volatile("cp.async.commit_group;");
    asm volatile("cp.async.wait_group 0;" ::: "memory");
}

__device__ __forceinline__ uint32_t swz(int row, int g, int ROWB) {
    int c = (g & ~7) | ((g ^ row) & 7);
    return (uint32_t)(row * ROWB + c * 16);
}

__device__ __forceinline__ void split_scalar(float w, uint16_t& hb, uint16_t& lb) {
    __nv_bfloat16 h = __float2bfloat16(w);
    float r = w - __bfloat162float(h);
    __nv_bfloat16 l = __float2bfloat16(r);
    hb = *(uint16_t*)&h;
    lb = *(uint16_t*)&l;
}

// ---------------------------------------------------------------------------
// Prep: weight transpose+split AND fvs/pos activation split.
// ---------------------------------------------------------------------------
struct Prep8 {
    const float* W[8];
    int K[8], N[8], off[8];
    const float* fvs;
    const float* pos;
    int n;
};

__global__ void prep_kernel(Prep8 p) {
    const int tid0 = blockIdx.x * blockDim.x + threadIdx.x;
    const int stride = gridDim.x * blockDim.x;
    for (int m = 0; m < 8; m++) {
        const int K = p.K[m], N = p.N[m], tot = K * N, off = p.off[m];
        const float* W = p.W[m];
        for (int idx = tid0; idx < tot; idx += stride) {
            int n = idx / K, k = idx - n * K;
            split_scalar(W[(size_t)k * N + n], g_wthi[off + idx], g_wtlo[off + idx]);
        }
    }
    const int nf = p.n * 128;
    for (int idx = tid0; idx < nf; idx += stride)
        split_scalar(p.fvs[idx], g_fvh[idx], g_fvl[idx]);
    const int np = p.n * 64;
    for (int idx = tid0; idx < np; idx += stride)
        split_scalar(p.pos[idx], g_poh[idx], g_pol[idx]);
}

// ---------------------------------------------------------------------------
// Fused bf16x3 GEMM + el/er epilogue. A from pre-split bf16 planes (cp.async).
// ---------------------------------------------------------------------------
template <int K>
__global__ __launch_bounds__(256, 1) void tc_gemm_fused(
    const uint16_t* __restrict__ A1h, const uint16_t* __restrict__ A1l, int K1,
    const uint16_t* __restrict__ A2h, const uint16_t* __restrict__ A2l,
    const uint16_t* __restrict__ Bh, const uint16_t* __restrict__ Bl,
    const float* __restrict__ al, const float* __restrict__ ar,
    float* __restrict__ el, float* __restrict__ er,
    float* __restrict__ C1, float* __restrict__ C2, int M, int row0)
{
    constexpr int BN   = 256;
    constexpr int ROWB = K * 2;
    constexpr int NG   = K / 8;
    constexpr int WN   = 128;
    constexpr int NT   = WN / 8;
    constexpr int KS   = K / 16;
    constexpr int AOFF  = 0;
    constexpr int ALOFF = 128 * ROWB;
    constexpr int BOFF  = 2 * 128 * ROWB;

    extern __shared__ char smem[];
    const uint32_t sb  = smem_u32(smem);
    const uint32_t sAH = sb + AOFF;
    const uint32_t sAL = sb + ALOFF;
    const uint32_t sB  = sb + BOFF;

    const int t    = threadIdx.x;
    const int wid  = t >> 5;
    const int lane = t & 31;
    const int bm   = row0 + blockIdx.x * 128;
    const int K2   = K - K1;

    // B stage 1 (hi plane)
    for (int idx = t; idx < BN * NG; idx += 256) {
        int rn = idx / NG, g = idx - rn * NG;
        cpasync16(sB + swz(rn, g, ROWB), Bh + (size_t)rn * K + g * 8);
    }
    // A hi+lo planes (pure cp.async, zfill OOB rows)
    for (int idx = t; idx < 128 * NG; idx += 256) {
        int row = idx / NG, g = idx - row * NG, k0 = g * 8;
        int grow = bm + row;
        int ok = (grow < M) ? 16 : 0;
        int gr = (grow < M) ? grow : 0;
        const uint16_t *ph, *pl;
        if (k0 < K1) {
            ph = A1h + (size_t)gr * K1 + k0;
            pl = A1l + (size_t)gr * K1 + k0;
        } else {
            ph = A2h + (size_t)gr * K2 + (k0 - K1);
            pl = A2l + (size_t)gr * K2 + (k0 - K1);
        }
        uint32_t o = swz(row, g, ROWB);
        cpasync16z(sAH + o, ph, ok);
        cpasync16z(sAL + o, pl, ok);
    }
    cpasync_wait();
    __syncthreads();

    const int wm   = wid & 3;
    const int wn   = wid >> 2;
    const int lr   = lane & 7;
    const int sel  = lane >> 3;
    const int selb1 = sel & 1;
    const int selb2 = sel >> 1;
    const int rowA_base = wm * 32 + lr + selb1 * 8;
    const int rowB_base = wn * WN + lr + selb2 * 8;

    float acc[2][NT][4];
#pragma unroll
    for (int mt = 0; mt < 2; mt++)
#pragma unroll
        for (int nt = 0; nt < NT; nt++)
#pragma unroll
            for (int q = 0; q < 4; q++) acc[mt][nt][q] = 0.f;

    // stage 1: Ah*Bh + Al*Bh
#pragma unroll
    for (int ks = 0; ks < KS; ks++) {
        uint32_t bfr[NT][2];
#pragma unroll
        for (int nt2 = 0; nt2 < NT / 2; nt2++) {
            uint32_t r[4];
            ldsm_x4(r, sB + swz(rowB_base + nt2 * 16, ks * 2 + selb1, ROWB));
            bfr[2 * nt2][0]     = r[0];
            bfr[2 * nt2][1]     = r[1];
            bfr[2 * nt2 + 1][0] = r[2];
            bfr[2 * nt2 + 1][1] = r[3];
        }
        uint32_t afr[2][4];
#pragma unroll
        for (int mt = 0; mt < 2; mt++)
            ldsm_x4(afr[mt], sAH + swz(rowA_base + mt * 16, ks * 2 + selb2, ROWB));
#pragma unroll
        for (int mt = 0; mt < 2; mt++)
#pragma unroll
            for (int nt = 0; nt < NT; nt++)
                mma16816(acc[mt][nt], afr[mt], bfr[nt]);
#pragma unroll
        for (int mt = 0; mt < 2; mt++)
            ldsm_x4(afr[mt], sAL + swz(rowA_base + mt * 16, ks * 2 + selb2, ROWB));
#pragma unroll
        for (int mt = 0; mt < 2; mt++)
#pragma unroll
            for (int nt = 0; nt < NT; nt++)
                mma16816(acc[mt][nt], afr[mt], bfr[nt]);
    }

    __syncthreads();
    for (int idx = t; idx < BN * NG; idx += 256) {
        int rn = idx / NG, g = idx - rn * NG;
        cpasync16(sB + swz(rn, g, ROWB), Bl + (size_t)rn * K + g * 8);
    }
    cpasync_wait();
    __syncthreads();

    // stage 2: Ah*Bl
#pragma unroll
    for (int ks = 0; ks < KS; ks++) {
        uint32_t bfr[NT][2];
#pragma unroll
        for (int nt2 = 0; nt2 < NT / 2; nt2++) {
            uint32_t r[4];
            ldsm_x4(r, sB + swz(rowB_base + nt2 * 16, ks * 2 + selb1, ROWB));
            bfr[2 * nt2][0]     = r[0];
            bfr[2 * nt2][1]     = r[1];
            bfr[2 * nt2 + 1][0] = r[2];
            bfr[2 * nt2 + 1][1] = r[3];
        }
        uint32_t afr[2][4];
#pragma unroll
        for (int mt = 0; mt < 2; mt++)
            ldsm_x4(afr[mt], sAH + swz(rowA_base + mt * 16, ks * 2 + selb2, ROWB));
#pragma unroll
        for (int mt = 0; mt < 2; mt++)
#pragma unroll
            for (int nt = 0; nt < NT; nt++)
                mma16816(acc[mt][nt], afr[mt], bfr[nt]);
    }

    float* __restrict__ C = (wn == 0) ? C1 : C2;
    const int colb = (lane & 3) * 2;
#pragma unroll
    for (int mt = 0; mt < 2; mt++) {
        int r0 = bm + wm * 32 + mt * 16 + (lane >> 2);
        int r1 = r0 + 8;
#pragma unroll
        for (int nt = 0; nt < NT; nt++) {
            int col = colb + nt * 8;
            if (r0 < M) *(float2*)&C[(size_t)r0 * 128 + col] =
                make_float2(acc[mt][nt][0], acc[mt][nt][1]);
            if (r1 < M) *(float2*)&C[(size_t)r1 * 128 + col] =
                make_float2(acc[mt][nt][2], acc[mt][nt][3]);
        }
    }

    if (wn == 0) {
#pragma unroll
        for (int mt = 0; mt < 2; mt++) {
            float e[8];
#pragma unroll
            for (int q = 0; q < 8; q++) e[q] = 0.f;
#pragma unroll
            for (int nt = 0; nt < NT; nt++) {
                int c = colb + nt * 8;
                float a0 = al[c], a1 = al[c + 1];
                float b0 = ar[c], b1 = ar[c + 1];
                float sl0 = acc[mt][nt][0] * a0 + acc[mt][nt][1] * a1;
                float sl1 = acc[mt][nt][2] * a0 + acc[mt][nt][3] * a1;
                float sr0 = acc[mt][nt][0] * b0 + acc[mt][nt][1] * b1;
                float sr1 = acc[mt][nt][2] * b0 + acc[mt][nt][3] * b1;
                int hsel = (nt < 8) ? 0 : 1;
                e[hsel]     += sl0;
                e[2 + hsel] += sr0;
                e[4 + hsel] += sl1;
                e[6 + hsel] += sr1;
            }
#pragma unroll
            for (int o = 1; o <= 2; o <<= 1)
#pragma unroll
                for (int q = 0; q < 8; q++)
                    e[q] += __shfl_xor_sync(0xffffffffu, e[q], o);
            if ((lane & 3) == 0) {
                int r0 = bm + wm * 32 + mt * 16 + (lane >> 2);
                int r1 = r0 + 8;
                if (r0 < M) {
                    el[2 * r0] = e[0]; el[2 * r0 + 1] = e[1];
                    er[2 * r0] = e[2]; er[2 * r0 + 1] = e[3];
                }
                if (r1 < M) {
                    el[2 * r1] = e[4]; el[2 * r1 + 1] = e[5];
                    er[2 * r1] = e[6]; er[2 * r1 + 1] = e[7];
                }
            }
        }
    }
}

// ---------------------------------------------------------------------------
// Small bf16x3 GEMM (pg layers), A from planes, fused el/er epilogue.
// ---------------------------------------------------------------------------
template <int BN, int K>
__global__ __launch_bounds__(256, 1) void tc_gemm_small(
    const uint16_t* __restrict__ Ah, const uint16_t* __restrict__ Al,
    const uint16_t* __restrict__ Bh, const uint16_t* __restrict__ Bl,
    const float* __restrict__ al, const float* __restrict__ ar,
    float* __restrict__ el, float* __restrict__ er,
    float* __restrict__ C, int M)
{
    constexpr int ROWB = K * 2;
    constexpr int NG   = K / 8;
    constexpr int WN   = BN / 2;
    constexpr int NT   = WN / 8;
    constexpr int KS   = K / 16;

    extern __shared__ char smem[];
    const uint32_t sAH = smem_u32(smem);
    const uint32_t sAL = sAH + 128 * ROWB;
    const uint32_t sBH = sAL + 128 * ROWB;
    const uint32_t sBL = sBH + BN * ROWB;

    const int t    = threadIdx.x;
    const int wid  = t >> 5;
    const int lane = t & 31;
    const int bm   = blockIdx.x * 128;

    for (int idx = t; idx < BN * NG; idx += 256) {
        int rn = idx / NG, g = idx - rn * NG, k0 = g * 8;
        cpasync16(sBH + swz(rn, g, ROWB), Bh + (size_t)rn * K + k0);
        cpasync16(sBL + swz(rn, g, ROWB), Bl + (size_t)rn * K + k0);
    }
    for (int idx = t; idx < 128 * NG; idx += 256) {
        int row = idx / NG, g = idx - row * NG, k0 = g * 8;
        int grow = bm + row;
        int ok = (grow < M) ? 16 : 0;
        int gr = (grow < M) ? grow : 0;
        uint32_t o = swz(row, g, ROWB);
        cpasync16z(sAH + o, Ah + (size_t)gr * K + k0, ok);
        cpasync16z(sAL + o, Al + (size_t)gr * K + k0, ok);
    }
    cpasync_wait();
    __syncthreads();

    const int wm = wid & 3;
    const int wn = wid >> 2;
    const int lr   = lane & 7;
    const int sel  = lane >> 3;
    const int selb1 = sel & 1;
    const int selb2 = sel >> 1;
    const int rowA_base = wm * 32 + lr + selb1 * 8;
    const int rowB_base = wn * WN + lr + selb2 * 8;

    float acc[2][NT][4];
#pragma unroll
    for (int mt = 0; mt < 2; mt++)
#pragma unroll
        for (int nt = 0; nt < NT; nt++)
#pragma unroll
            for (int q = 0; q < 4; q++) acc[mt][nt][q] = 0.f;

#pragma unroll
    for (int pr = 0; pr < 3; pr++) {
        const uint32_t baseA = (pr == 2) ? sAL : sAH;
        const uint32_t baseB = (pr == 1) ? sBL : sBH;
#pragma unroll
        for (int ks = 0; ks < KS; ks++) {
            uint32_t afr[2][4];
#pragma unroll
            for (int mt = 0; mt < 2; mt++)
                ldsm_x4(afr[mt], baseA + swz(rowA_base + mt * 16, ks * 2 + selb2, ROWB));
            uint32_t bfr[NT][2];
#pragma unroll
            for (int nt2 = 0; nt2 < NT / 2; nt2++) {
                uint32_t r[4];
                ldsm_x4(r, baseB + swz(rowB_base + nt2 * 16, ks * 2 + selb1, ROWB));
                bfr[2 * nt2][0]     = r[0];
                bfr[2 * nt2][1]     = r[1];
                bfr[2 * nt2 + 1][0] = r[2];
                bfr[2 * nt2 + 1][1] = r[3];
            }
#pragma unroll
            for (int mt = 0; mt < 2; mt++)
#pragma unroll
                for (int nt = 0; nt < NT; nt++)
                    mma16816(acc[mt][nt], afr[mt], bfr[nt]);
        }
    }

    const int colb = wn * WN + (lane & 3) * 2;
#pragma unroll
    for (int mt = 0; mt < 2; mt++) {
        int r0 = bm + wm * 32 + mt * 16 + (lane >> 2);
        int r1 = r0 + 8;
#pragma unroll
        for (int nt = 0; nt < NT; nt++) {
            int col = colb + nt * 8;
            if (r0 < M) *(float2*)&C[(size_t)r0 * BN + col] =
                make_float2(acc[mt][nt][0], acc[mt][nt][1]);
            if (r1 < M) *(float2*)&C[(size_t)r1 * BN + col] =
                make_float2(acc[mt][nt][2], acc[mt][nt][3]);
        }
    }

#pragma unroll
    for (int mt = 0; mt < 2; mt++) {
        float e[4];
#pragma unroll
        for (int q = 0; q < 4; q++) e[q] = 0.f;
#pragma unroll
        for (int nt = 0; nt < NT; nt++) {
            int c = colb + nt * 8;
            float a0 = al[c], a1 = al[c + 1];
            float b0 = ar[c], b1 = ar[c + 1];
            e[0] += acc[mt][nt][0] * a0 + acc[mt][nt][1] * a1;
            e[1] += acc[mt][nt][0] * b0 + acc[mt][nt][1] * b1;
            e[2] += acc[mt][nt][2] * a0 + acc[mt][nt][3] * a1;
            e[3] += acc[mt][nt][2] * b0 + acc[mt][nt][3] * b1;
        }
#pragma unroll
        for (int o = 1; o <= 2; o <<= 1)
#pragma unroll
            for (int q = 0; q < 4; q++)
                e[q] += __shfl_xor_sync(0xffffffffu, e[q], o);
        if ((lane & 3) == 0) {
            int r0 = bm + wm * 32 + mt * 16 + (lane >> 2);
            int r1 = r0 + 8;
            if (r0 < M) { el[2 * r0 + wn] = e[0]; er[2 * r0 + wn] = e[1]; }
            if (r1 < M) { el[2 * r1 + wn] = e[2]; er[2 * r1 + wn] = e[3]; }
        }
    }
}

// ---------------------------------------------------------------------------
// CSR build
// ---------------------------------------------------------------------------
__global__ void count_kernel(const int* __restrict__ dst, int e) {
    int i = blockIdx.x * blockDim.x + threadIdx.x;
    if (i < e) atomicAdd(&g_cnt[dst[i]], 1);
}

__global__ void scan_kernel(int n) {
    __shared__ int partial[1024];
    const int t = threadIdx.x;
    const int C = (n + 1023) / 1024;
    int s = 0;
    for (int j = 0; j < C; j++) {
        int idx = t * C + j;
        if (idx < n) s += g_cnt[idx];
    }
    partial[t] = s;
    __syncthreads();
    for (int ofs = 1; ofs < 1024; ofs <<= 1) {
        int v = (t >= ofs) ? partial[t - ofs] : 0;
        __syncthreads();
        partial[t] += v;
        __syncthreads();
    }
    int run = (t == 0) ? 0 : partial[t - 1];
    for (int j = 0; j < C; j++) {
        int idx = t * C + j;
        if (idx < n) {
            g_off[idx] = run;
            run += g_cnt[idx];
            g_cnt[idx] = 0;
        }
    }
    if (t == 1023) g_off[n] = run;
}

__global__ void fill_kernel(const int* __restrict__ src, const int* __restrict__ dst, int e) {
    int i = blockIdx.x * blockDim.x + threadIdx.x;
    if (i < e) {
        int d = dst[i];
        int p = atomicAdd(&g_cnt[d], 1);
        g_esrc[g_off[d] + p] = src[i];
    }
}

// ---------------------------------------------------------------------------
// Aggregation (single-pass online softmax, fp32 gather).
// OUTMODE: 0 = headmean fp32 out; 1 = bf16 hi/lo planes only; 2 = fp32 + planes.
// ACT: 0 = elu, 1 = tanh.
// ---------------------------------------------------------------------------
__device__ __forceinline__ float leaky02(float x) { return x > 0.f ? x : 0.2f * x; }

template <int HD, int ACT, int OUTMODE>
__global__ void agg_kernel(const float* __restrict__ h,
                           const float* __restrict__ res,
                           const float* __restrict__ elp,
                           const float* __restrict__ erp,
                           float* __restrict__ out,
                           uint16_t* __restrict__ outh,
                           uint16_t* __restrict__ outl,
                           int node0, int cnt)
{
    constexpr int V = HD / 32;
    int node = node0 + ((blockIdx.x * blockDim.x + threadIdx.x) >> 5);
    int lane = threadIdx.x & 31;
    if (node >= node0 + cnt) return;

    const int beg = g_off[node];
    const int end = g_off[node + 1];
    const float2 erv = ((const float2*)erp)[node];
    const float2* __restrict__ el2 = (const float2*)elp;
    const int* __restrict__ esrc = g_esrc;

    const bool head0 = (lane * V) < (HD / 2);
    float m0 = -1e30f, m1 = -1e30f;
    float d0 = 0.f, d1 = 0.f;
    float acc[V];
#pragma unroll
    for (int q = 0; q < V; q++) acc[q] = 0.f;

    int i = beg;
    for (; i + 4 <= end; i += 4) {
        int s[4];
#pragma unroll
        for (int j = 0; j < 4; j++) s[j] = esrc[i + j];
        float2 ev[4];
#pragma unroll
        for (int j = 0; j < 4; j++) ev[j] = el2[s[j]];
        float hv[4][V];
#pragma unroll
        for (int j = 0; j < 4; j++) {
            if (V == 4) *(float4*)hv[j] = *(const float4*)(h + (size_t)s[j] * HD + lane * V);
            else        *(float2*)hv[j] = *(const float2*)(h + (size_t)s[j] * HD + lane * V);
        }
#pragma unroll
        for (int j = 0; j < 4; j++) {
            float e0 = leaky02(ev[j].x + erv.x);
            float e1 = leaky02(ev[j].y + erv.y);
            float nm0 = fmaxf(m0, e0), nm1 = fmaxf(m1, e1);
            float sc0 = __expf(m0 - nm0), w0 = __expf(e0 - nm0);
            float sc1 = __expf(m1 - nm1), w1 = __expf(e1 - nm1);
            d0 = d0 * sc0 + w0;
            d1 = d1 * sc1 + w1;
            m0 = nm0; m1 = nm1;
            float scv = head0 ? sc0 : sc1;
            float wv  = head0 ? w0  : w1;
#pragma unroll
            for (int q = 0; q < V; q++) acc[q] = fmaf(acc[q], scv, wv * hv[j][q]);
        }
    }
    for (; i < end; i++) {
        int s = esrc[i];
        float2 ev = el2[s];
        float hv[V];
        if (V == 4) *(float4*)hv = *(const float4*)(h + (size_t)s * HD + lane * V);
        else        *(float2*)hv = *(const float2*)(h + (size_t)s * HD + lane * V);
        float e0 = leaky02(ev.x + erv.x);
        float e1 = leaky02(ev.y + erv.y);
        float nm0 = fmaxf(m0, e0), nm1 = fmaxf(m1, e1);
        float sc0 = __expf(m0 - nm0), w0 = __expf(e0 - nm0);
        float sc1 = __expf(m1 - nm1), w1 = __expf(e1 - nm1);
        d0 = d0 * sc0 + w0;
        d1 = d1 * sc1 + w1;
        m0 = nm0; m1 = nm1;
        float scv = head0 ? sc0 : sc1;
        float wv  = head0 ? w0  : w1;
#pragma unroll
        for (int q = 0; q < V; q++) acc[q] = fmaf(acc[q], scv, wv * hv[q]);
    }

    const bool has = (end > beg);
    const float inv0 = has ? 1.f / d0 : 0.f;
    const float inv1 = has ? 1.f / d1 : 0.f;
    const float invv = head0 ? inv0 : inv1;

    float rr[V];
    if (V == 4) *(float4*)rr = *(const float4*)(res + (size_t)node * HD + lane * V);
    else        *(float2*)rr = *(const float2*)(res + (size_t)node * HD + lane * V);

    float v[V];
#pragma unroll
    for (int q = 0; q < V; q++) {
        v[q] = acc[q] * invv + rr[q];
        if (ACT == 0) v[q] = v[q] > 0.f ? v[q] : expm1f(v[q]);
        else          v[q] = tanhf(v[q]);
    }

    if (OUTMODE == 0) {
        // headmean: combine col c (lanes 0-15) with c+64 (lanes 16-31)
        float p[V];
#pragma unroll
        for (int q = 0; q < V; q++) p[q] = __shfl_xor_sync(0xffffffffu, v[q], 16);
        if (lane < 16) {
            float o[V];
#pragma unroll
            for (int q = 0; q < V; q++) o[q] = 0.5f * (v[q] + p[q]);
            if (V == 4) *(float4*)(out + (size_t)node * 64 + lane * V) = *(float4*)o;
            else        *(float2*)(out + (size_t)node * 64 + lane * V) = *(float2*)o;
        }
    } else {
        if (OUTMODE == 2) {
            if (V == 4) *(float4*)(out + (size_t)node * HD + lane * V) = *(float4*)v;
            else        *(float2*)(out + (size_t)node * HD + lane * V) = *(float2*)v;
        }
        // bf16 hi/lo plane stores
        uint16_t hb[V], lb[V];
#pragma unroll
        for (int q = 0; q < V; q++) split_scalar(v[q], hb[q], lb[q]);
        if (V == 4) {
            *(uint2*)(outh + (size_t)node * HD + lane * V) = *(uint2*)hb;
            *(uint2*)(outl + (size_t)node * HD + lane * V) = *(uint2*)lb;
        } else {
            *(uint32_t*)(outh + (size_t)node * HD + lane * V) = *(uint32_t*)hb;
            *(uint32_t*)(outl + (size_t)node * HD + lane * V) = *(uint32_t*)lb;
        }
    }
}

// ---------------------------------------------------------------------------
// Launch — 3-chunk agg→gemm pipeline per boundary, ping-pong buffers,
// all GEMM A-operands pre-split into bf16 planes.
// ---------------------------------------------------------------------------
extern "C" void kernel_launch(void* const* d_in, const int* in_sizes, int n_in,
                              void* d_out, int out_size)
{
    const float* fvs = (const float*)d_in[0];
    const float* pos = (const float*)d_in[1];
    const int*   src = (const int*)d_in[2];
    const int*   dst = (const int*)d_in[3];
    const float* g0W  = (const float*)d_in[4];
    const float* g0al = (const float*)d_in[5];
    const float* g0ar = (const float*)d_in[6];
    const float* g0rW = (const float*)d_in[7];
    const float* g1W  = (const float*)d_in[8];
    const float* g1al = (const float*)d_in[9];
    const float* g1ar = (const float*)d_in[10];
    const float* g1rW = (const float*)d_in[11];
    const float* g2W  = (const float*)d_in[12];
    const float* g2al = (const float*)d_in[13];
    const float* g2ar = (const float*)d_in[14];
    const float* g2rW = (const float*)d_in[15];
    const float* p0W  = (const float*)d_in[16];
    const float* p0al = (const float*)d_in[17];
    const float* p0ar = (const float*)d_in[18];
    const float* p1W  = (const float*)d_in[19];
    const float* p1al = (const float*)d_in[20];
    const float* p1ar = (const float*)d_in[21];

    const int n = in_sizes[0] / 128;
    const int e = in_sizes[2];

    float *hb, *rhb, *elb, *erb, *hp, *hq, *el2, *er2;
    int* cnt;
    uint16_t *wthi, *wtlo;
    uint16_t *fvh, *fvl, *poh, *pol, *hsh, *hsl, *hs2h, *hs2l, *hph, *hpl, *ohph, *ohpl;
    cudaGetSymbolAddress((void**)&hb,   g_h);
    cudaGetSymbolAddress((void**)&rhb,  g_rh);
    cudaGetSymbolAddress((void**)&elb,  g_el);
    cudaGetSymbolAddress((void**)&erb,  g_er);
    cudaGetSymbolAddress((void**)&hp,   g_hp);
    cudaGetSymbolAddress((void**)&hq,   g_hq);
    cudaGetSymbolAddress((void**)&el2,  g_el2);
    cudaGetSymbolAddress((void**)&er2,  g_er2);
    cudaGetSymbolAddress((void**)&cnt,  g_cnt);
    cudaGetSymbolAddress((void**)&wthi, g_wthi);
    cudaGetSymbolAddress((void**)&wtlo, g_wtlo);
    cudaGetSymbolAddress((void**)&fvh,  g_fvh);
    cudaGetSymbolAddress((void**)&fvl,  g_fvl);
    cudaGetSymbolAddress((void**)&poh,  g_poh);
    cudaGetSymbolAddress((void**)&pol,  g_pol);
    cudaGetSymbolAddress((void**)&hsh,  g_hsh);
    cudaGetSymbolAddress((void**)&hsl,  g_hsl);
    cudaGetSymbolAddress((void**)&hs2h, g_hs2h);
    cudaGetSymbolAddress((void**)&hs2l, g_hs2l);
    cudaGetSymbolAddress((void**)&hph,  g_hph);
    cudaGetSymbolAddress((void**)&hpl,  g_hpl);
    cudaGetSymbolAddress((void**)&ohph, g_ohph);
    cudaGetSymbolAddress((void**)&ohpl, g_ohpl);

    float* h0  = hb;                       float* h1  = hb  + (size_t)NMAX * 128;
    float* rh0 = rhb;                      float* rh1 = rhb + (size_t)NMAX * 128;
    float* el0 = elb;                      float* el1 = elb + (size_t)NMAX * 2;
    float* er0 = erb;                      float* er1 = erb + (size_t)NMAX * 2;

    float* out_hs = (float*)d_out;
    float* out_hp = (float*)d_out + (size_t)n * 64;

    const int EB = (e + 255) / 256;
    const int GB = (n + 127) / 128;
    const int WB = (n + 7) / 8;

    const int CH = ((n / 3 + 127) / 128) * 128;
    int c0[3], cc[3];
    c0[0] = 0;      cc[0] = CH;
    c0[1] = CH;     cc[1] = CH;
    c0[2] = 2 * CH; cc[2] = n - 2 * CH;

    constexpr int SMEM_F     = 2 * 128 * 384 + 256 * 384;
    constexpr int SMEM_SMALL = (128 + 128 + 64 + 64) * 64 * 2;
    cudaFuncSetAttribute(tc_gemm_fused<192>,    cudaFuncAttributeMaxDynamicSharedMemorySize, SMEM_F);
    cudaFuncSetAttribute(tc_gemm_small<64, 64>, cudaFuncAttributeMaxDynamicSharedMemorySize, SMEM_SMALL);

    static cudaStream_t s1 = nullptr, s2 = nullptr, s3 = nullptr;
    static cudaEvent_t evFork, evPrep, evCSR, evP0, evP1, evG0, evG1;
    static cudaEvent_t evA0[3], evA1[3], evEnd1, evEnd2;
    if (s1 == nullptr) {
        cudaStreamCreateWithFlags(&s1, cudaStreamNonBlocking);
        cudaStreamCreateWithFlags(&s2, cudaStreamNonBlocking);
        cudaStreamCreateWithFlags(&s3, cudaStreamNonBlocking);
        cudaEventCreateWithFlags(&evFork, cudaEventDisableTiming);
        cudaEventCreateWithFlags(&evPrep, cudaEventDisableTiming);
        cudaEventCreateWithFlags(&evCSR,  cudaEventDisableTiming);
        cudaEventCreateWithFlags(&evP0,   cudaEventDisableTiming);
        cudaEventCreateWithFlags(&evP1,   cudaEventDisableTiming);
        cudaEventCreateWithFlags(&evG0,   cudaEventDisableTiming);
        cudaEventCreateWithFlags(&evG1,   cudaEventDisableTiming);
        for (int i = 0; i < 3; i++) {
            cudaEventCreateWithFlags(&evA0[i], cudaEventDisableTiming);
            cudaEventCreateWithFlags(&evA1[i], cudaEventDisableTiming);
        }
        cudaEventCreateWithFlags(&evEnd1, cudaEventDisableTiming);
        cudaEventCreateWithFlags(&evEnd2, cudaEventDisableTiming);
    }

    Prep8 pa;
    const float* Ws[8] = {g0W, g0rW, g1W, g1rW, g2W, g2rW, p0W, p1W};
    for (int m = 0; m < 8; m++) {
        pa.W[m] = Ws[m];
        pa.K[m] = (m < 6) ? 192 : 64;
        pa.N[m] = (m < 6) ? 128 : 64;
        pa.off[m] = (m < 6) ? (m >> 1) * WT_FUSED + (m & 1) * (128 * 192)
                            : 3 * WT_FUSED + (m - 6) * WT_SMALL;
    }
    pa.fvs = fvs;
    pa.pos = pos;
    pa.n   = n;

    const int F0 = 0 * WT_FUSED, F1 = 1 * WT_FUSED, F2 = 2 * WT_FUSED;
    const int P0 = 3 * WT_FUSED, P1 = 3 * WT_FUSED + WT_SMALL;

    // ---- fork ----
    cudaEventRecord(evFork, 0);
    cudaStreamWaitEvent(s1, evFork, 0);
    cudaStreamWaitEvent(s2, evFork, 0);
    cudaStreamWaitEvent(s3, evFork, 0);

    prep_kernel<<<296, 256, 0, s1>>>(pa);
    cudaEventRecord(evPrep, s1);
    cudaStreamWaitEvent(s2, evPrep, 0);

    // s0: CSR build (hidden under prep + gemmF0)
    cudaMemsetAsync(cnt, 0, (size_t)n * sizeof(int), 0);
    count_kernel<<<EB, 256, 0, 0>>>(dst, e);
    scan_kernel<<<1, 1024, 0, 0>>>(n);
    fill_kernel<<<EB, 256, 0, 0>>>(src, dst, e);
    cudaEventRecord(evCSR, 0);

    // ---- layer 0 GEMMs (write buffer 0) ----
    tc_gemm_fused<192><<<GB, 256, SMEM_F, s1>>>(
        fvh, fvl, 128, poh, pol, wthi + F0, wtlo + F0,
        g0al, g0ar, el0, er0, h0, rh0, n, 0);
    cudaEventRecord(evG0, s1);
    tc_gemm_small<64, 64><<<GB, 256, SMEM_SMALL, s2>>>(
        poh, pol, wthi + P0, wtlo + P0, p0al, p0ar, el2, er2, hq, n);
    cudaStreamWaitEvent(s2, evCSR, 0);
    agg_kernel<64, 1, 2><<<WB, 256, 0, s2>>>(hq, pos, el2, er2, hp, hph, hpl, 0, n);
    cudaEventRecord(evP0, s2);

    // ---- boundary 0: agg0 chunks on s3 (write hs planes), gemmF1 trails ----
    cudaStreamWaitEvent(s3, evCSR, 0);
    cudaStreamWaitEvent(s3, evG0, 0);
    for (int i = 0; i < 3; i++) {
        agg_kernel<128, 0, 1><<<(cc[i] + 7) / 8, 256, 0, s3>>>(
            h0, rh0, el0, er0, nullptr, hsh, hsl, c0[i], cc[i]);
        cudaEventRecord(evA0[i], s3);
    }
    cudaStreamWaitEvent(s1, evP0, 0);          // gemmF1 needs hp planes
    for (int i = 0; i < 3; i++) {
        cudaStreamWaitEvent(s1, evA0[i], 0);
        tc_gemm_fused<192><<<(cc[i] + 127) / 128, 256, SMEM_F, s1>>>(
            hsh, hsl, 128, hph, hpl, wthi + F1, wtlo + F1,
            g1al, g1ar, el1, er1, h1, rh1, n, c0[i]);
    }
    cudaEventRecord(evG1, s1);

    // pg layer 1 (s2, overlaps boundary 0)
    tc_gemm_small<64, 64><<<GB, 256, SMEM_SMALL, s2>>>(
        hph, hpl, wthi + P1, wtlo + P1, p1al, p1ar, el2, er2, hq, n);
    agg_kernel<64, 1, 2><<<WB, 256, 0, s2>>>(hq, hp, el2, er2, out_hp, ohph, ohpl, 0, n);
    cudaEventRecord(evP1, s2);

    // ---- boundary 1: agg1 chunks (read buf1, need ALL gemmF1 chunks) ----
    cudaStreamWaitEvent(s3, evG1, 0);
    for (int i = 0; i < 3; i++) {
        agg_kernel<128, 0, 1><<<(cc[i] + 7) / 8, 256, 0, s3>>>(
            h1, rh1, el1, er1, nullptr, hs2h, hs2l, c0[i], cc[i]);
        cudaEventRecord(evA1[i], s3);
    }
    cudaStreamWaitEvent(s1, evP1, 0);          // gemmF2 needs out_hp planes
    for (int i = 0; i < 3; i++) {
        cudaStreamWaitEvent(s1, evA1[i], 0);
        tc_gemm_fused<192><<<(cc[i] + 127) / 128, 256, SMEM_F, s1>>>(
            hs2h, hs2l, 128, ohph, ohpl, wthi + F2, wtlo + F2,
            g2al, g2ar, el0, er0, h0, rh0, n, c0[i]);
    }

    // ---- final agg (headmean; needs all gemmF2 chunks — stream order on s1) ----
    agg_kernel<128, 0, 0><<<WB, 256, 0, s1>>>(h0, rh0, el0, er0, out_hs,
                                              nullptr, nullptr, 0, n);
    cudaEventRecord(evEnd1, s1);
    cudaEventRecord(evEnd2, s2);

    // ---- join ----
    cudaStreamWaitEvent(0, evEnd1, 0);
    cudaStreamWaitEvent(0, evEnd2, 0);
}

// round 16
// speedup vs baseline: 1.0146x; 1.0146x over previous
#include <cuda_runtime.h>
#include <cuda_bf16.h>
#include <math.h>
#include <stdint.h>

// ---------------------------------------------------------------------------
// Problem constants
// ---------------------------------------------------------------------------
#define NMAX 50000
#define EMAX 800000

// ---------------------------------------------------------------------------
// Scratch (device globals) — gat-chain h/rh/el/er double-buffered.
// ---------------------------------------------------------------------------
__device__ float g_h  [2][(size_t)NMAX * 128];
__device__ float g_rh [2][(size_t)NMAX * 128];
__device__ float g_el [2][(size_t)NMAX * 2];
__device__ float g_er [2][(size_t)NMAX * 2];
__device__ float g_hs [(size_t)NMAX * 128];
__device__ float g_hs2[(size_t)NMAX * 128];
__device__ float g_hp [(size_t)NMAX * 64];
__device__ float g_hq [(size_t)NMAX * 64];
__device__ float g_el2[(size_t)NMAX * 2];
__device__ float g_er2[(size_t)NMAX * 2];
__device__ int   g_off[NMAX + 1];
__device__ int   g_cnt[NMAX];
__device__ int   g_esrc[EMAX];

#define WT_FUSED (256 * 192)
#define WT_SMALL (64 * 64)
__device__ uint16_t g_wthi[3 * WT_FUSED + 2 * WT_SMALL];
__device__ uint16_t g_wtlo[3 * WT_FUSED + 2 * WT_SMALL];

// ---------------------------------------------------------------------------
// Helpers
// ---------------------------------------------------------------------------
__device__ __forceinline__ uint32_t smem_u32(const void* p) {
    uint32_t a;
    asm("{ .reg .u64 t; cvta.to.shared.u64 t, %1; cvt.u32.u64 %0, t; }"
        : "=r"(a) : "l"(p));
    return a;
}

__device__ __forceinline__ void ldsm_x4(uint32_t* r, uint32_t addr) {
    asm volatile("ldmatrix.sync.aligned.m8n8.x4.shared.b16 {%0,%1,%2,%3}, [%4];"
                 : "=r"(r[0]), "=r"(r[1]), "=r"(r[2]), "=r"(r[3]) : "r"(addr));
}

__device__ __forceinline__ void mma16816(float* c, const uint32_t* a, const uint32_t* b) {
    asm volatile(
        "mma.sync.aligned.m16n8k16.row.col.f32.bf16.bf16.f32 "
        "{%0,%1,%2,%3}, {%4,%5,%6,%7}, {%8,%9}, {%0,%1,%2,%3};"
        : "+f"(c[0]), "+f"(c[1]), "+f"(c[2]), "+f"(c[3])
        : "r"(a[0]), "r"(a[1]), "r"(a[2]), "r"(a[3]), "r"(b[0]), "r"(b[1]));
}

__device__ __forceinline__ void cpasync16(uint32_t s, const void* g) {
    asm volatile("cp.async.cg.shared.global [%0], [%1], 16;" :: "r"(s), "l"(g));
}
__device__ __forceinline__ void cpasync_wait() {
    asm volatile("cp.async.commit_group;");
    asm volatile("cp.async.wait_group 0;" ::: "memory");
}

__device__ __forceinline__ void split8(const float* v, uint4& h4, uint4& l4) {
    uint16_t* hp = (uint16_t*)&h4;
    uint16_t* lp = (uint16_t*)&l4;
#pragma unroll
    for (int i = 0; i < 8; i++) {
        __nv_bfloat16 hb = __float2bfloat16(v[i]);
        float r = v[i] - __bfloat162float(hb);
        __nv_bfloat16 lb = __float2bfloat16(r);
        hp[i] = *(uint16_t*)&hb;
        lp[i] = *(uint16_t*)&lb;
    }
}

__device__ __forceinline__ uint32_t swz(int row, int g, int ROWB) {
    int c = (g & ~7) | ((g ^ row) & 7);
    return (uint32_t)(row * ROWB + c * 16);
}

// ---------------------------------------------------------------------------
// Weight prep
// ---------------------------------------------------------------------------
struct Prep8 {
    const float* W[8];
    int K[8], N[8], off[8];
};

__global__ void prep_kernel(Prep8 p) {
    for (int m = 0; m < 8; m++) {
        const int K = p.K[m], N = p.N[m], tot = K * N, off = p.off[m];
        const float* W = p.W[m];
        for (int idx = blockIdx.x * blockDim.x + threadIdx.x; idx < tot;
             idx += gridDim.x * blockDim.x) {
            int n = idx / K, k = idx - n * K;
            float w = W[(size_t)k * N + n];
            __nv_bfloat16 h = __float2bfloat16(w);
            float r = w - __bfloat162float(h);
            __nv_bfloat16 l = __float2bfloat16(r);
            g_wthi[off + idx] = *(uint16_t*)&h;
            g_wtlo[off + idx] = *(uint16_t*)&l;
        }
    }
}

// ---------------------------------------------------------------------------
// Fused bf16x3 GEMM + el/er epilogue (gat chain). row0 = M-tile base offset.
// ---------------------------------------------------------------------------
template <int K>
__global__ __launch_bounds__(256, 1) void tc_gemm_fused(
    const float* __restrict__ A1, int K1,
    const float* __restrict__ A2,
    const uint16_t* __restrict__ Bh, const uint16_t* __restrict__ Bl,
    const float* __restrict__ al, const float* __restrict__ ar,
    float* __restrict__ el, float* __restrict__ er,
    float* __restrict__ C1, float* __restrict__ C2, int M, int row0)
{
    constexpr int BN   = 256;
    constexpr int ROWB = K * 2;
    constexpr int NG   = K / 8;
    constexpr int WN   = 128;
    constexpr int NT   = WN / 8;
    constexpr int KS   = K / 16;
    constexpr int AOFF  = 0;
    constexpr int ALOFF = 128 * ROWB;
    constexpr int BOFF  = 2 * 128 * ROWB;

    extern __shared__ char smem[];
    const uint32_t sb  = smem_u32(smem);
    const uint32_t sAH = sb + AOFF;
    const uint32_t sAL = sb + ALOFF;
    const uint32_t sB  = sb + BOFF;

    const int t    = threadIdx.x;
    const int wid  = t >> 5;
    const int lane = t & 31;
    const int bm   = row0 + blockIdx.x * 128;

    for (int idx = t; idx < BN * NG; idx += 256) {
        int rn = idx / NG, g = idx - rn * NG;
        cpasync16(sB + swz(rn, g, ROWB), Bh + (size_t)rn * K + g * 8);
    }

    for (int idx = t; idx < 128 * NG; idx += 256) {
        int row = idx / NG, g = idx - row * NG, k0 = g * 8;
        int grow = bm + row;
        float v[8] = {0, 0, 0, 0, 0, 0, 0, 0};
        if (grow < M) {
            const float* p = (k0 < K1) ? (A1 + (size_t)grow * K1 + k0)
                                       : (A2 + (size_t)grow * (K - K1) + (k0 - K1));
            *(float4*)&v[0] = ((const float4*)p)[0];
            *(float4*)&v[4] = ((const float4*)p)[1];
        }
        uint4 h4, l4;
        split8(v, h4, l4);
        uint32_t o = swz(row, g, ROWB);
        *(uint4*)(smem + AOFF + o)  = h4;
        *(uint4*)(smem + ALOFF + o) = l4;
    }
    cpasync_wait();
    __syncthreads();

    const int wm   = wid & 3;
    const int wn   = wid >> 2;
    const int lr   = lane & 7;
    const int sel  = lane >> 3;
    const int selb1 = sel & 1;
    const int selb2 = sel >> 1;
    const int rowA_base = wm * 32 + lr + selb1 * 8;
    const int rowB_base = wn * WN + lr + selb2 * 8;

    float acc[2][NT][4];
#pragma unroll
    for (int mt = 0; mt < 2; mt++)
#pragma unroll
        for (int nt = 0; nt < NT; nt++)
#pragma unroll
            for (int q = 0; q < 4; q++) acc[mt][nt][q] = 0.f;

#pragma unroll
    for (int ks = 0; ks < KS; ks++) {
        uint32_t bfr[NT][2];
#pragma unroll
        for (int nt2 = 0; nt2 < NT / 2; nt2++) {
            uint32_t r[4];
            ldsm_x4(r, sB + swz(rowB_base + nt2 * 16, ks * 2 + selb1, ROWB));
            bfr[2 * nt2][0]     = r[0];
            bfr[2 * nt2][1]     = r[1];
            bfr[2 * nt2 + 1][0] = r[2];
            bfr[2 * nt2 + 1][1] = r[3];
        }
        uint32_t afr[2][4];
#pragma unroll
        for (int mt = 0; mt < 2; mt++)
            ldsm_x4(afr[mt], sAH + swz(rowA_base + mt * 16, ks * 2 + selb2, ROWB));
#pragma unroll
        for (int mt = 0; mt < 2; mt++)
#pragma unroll
            for (int nt = 0; nt < NT; nt++)
                mma16816(acc[mt][nt], afr[mt], bfr[nt]);
#pragma unroll
        for (int mt = 0; mt < 2; mt++)
            ldsm_x4(afr[mt], sAL + swz(rowA_base + mt * 16, ks * 2 + selb2, ROWB));
#pragma unroll
        for (int mt = 0; mt < 2; mt++)
#pragma unroll
            for (int nt = 0; nt < NT; nt++)
                mma16816(acc[mt][nt], afr[mt], bfr[nt]);
    }

    __syncthreads();
    for (int idx = t; idx < BN * NG; idx += 256) {
        int rn = idx / NG, g = idx - rn * NG;
        cpasync16(sB + swz(rn, g, ROWB), Bl + (size_t)rn * K + g * 8);
    }
    cpasync_wait();
    __syncthreads();

#pragma unroll
    for (int ks = 0; ks < KS; ks++) {
        uint32_t bfr[NT][2];
#pragma unroll
        for (int nt2 = 0; nt2 < NT / 2; nt2++) {
            uint32_t r[4];
            ldsm_x4(r, sB + swz(rowB_base + nt2 * 16, ks * 2 + selb1, ROWB));
            bfr[2 * nt2][0]     = r[0];
            bfr[2 * nt2][1]     = r[1];
            bfr[2 * nt2 + 1][0] = r[2];
            bfr[2 * nt2 + 1][1] = r[3];
        }
        uint32_t afr[2][4];
#pragma unroll
        for (int mt = 0; mt < 2; mt++)
            ldsm_x4(afr[mt], sAH + swz(rowA_base + mt * 16, ks * 2 + selb2, ROWB));
#pragma unroll
        for (int mt = 0; mt < 2; mt++)
#pragma unroll
            for (int nt = 0; nt < NT; nt++)
                mma16816(acc[mt][nt], afr[mt], bfr[nt]);
    }

    float* __restrict__ C = (wn == 0) ? C1 : C2;
    const int colb = (lane & 3) * 2;
#pragma unroll
    for (int mt = 0; mt < 2; mt++) {
        int r0 = bm + wm * 32 + mt * 16 + (lane >> 2);
        int r1 = r0 + 8;
#pragma unroll
        for (int nt = 0; nt < NT; nt++) {
            int col = colb + nt * 8;
            if (r0 < M) *(float2*)&C[(size_t)r0 * 128 + col] =
                make_float2(acc[mt][nt][0], acc[mt][nt][1]);
            if (r1 < M) *(float2*)&C[(size_t)r1 * 128 + col] =
                make_float2(acc[mt][nt][2], acc[mt][nt][3]);
        }
    }

    if (wn == 0) {
#pragma unroll
        for (int mt = 0; mt < 2; mt++) {
            float e[8];
#pragma unroll
            for (int q = 0; q < 8; q++) e[q] = 0.f;
#pragma unroll
            for (int nt = 0; nt < NT; nt++) {
                int c = colb + nt * 8;
                float a0 = al[c], a1 = al[c + 1];
                float b0 = ar[c], b1 = ar[c + 1];
                float sl0 = acc[mt][nt][0] * a0 + acc[mt][nt][1] * a1;
                float sl1 = acc[mt][nt][2] * a0 + acc[mt][nt][3] * a1;
                float sr0 = acc[mt][nt][0] * b0 + acc[mt][nt][1] * b1;
                float sr1 = acc[mt][nt][2] * b0 + acc[mt][nt][3] * b1;
                int hsel = (nt < 8) ? 0 : 1;
                e[hsel]     += sl0;
                e[2 + hsel] += sr0;
                e[4 + hsel] += sl1;
                e[6 + hsel] += sr1;
            }
#pragma unroll
            for (int o = 1; o <= 2; o <<= 1)
#pragma unroll
                for (int q = 0; q < 8; q++)
                    e[q] += __shfl_xor_sync(0xffffffffu, e[q], o);
            if ((lane & 3) == 0) {
                int r0 = bm + wm * 32 + mt * 16 + (lane >> 2);
                int r1 = r0 + 8;
                if (r0 < M) {
                    el[2 * r0] = e[0]; el[2 * r0 + 1] = e[1];
                    er[2 * r0] = e[2]; er[2 * r0 + 1] = e[3];
                }
                if (r1 < M) {
                    el[2 * r1] = e[4]; el[2 * r1 + 1] = e[5];
                    er[2 * r1] = e[6]; er[2 * r1 + 1] = e[7];
                }
            }
        }
    }
}

// ---------------------------------------------------------------------------
// Small bf16x3 GEMM (pg layers) with fused el/er epilogue
// ---------------------------------------------------------------------------
template <int BN, int K>
__global__ __launch_bounds__(256, 1) void tc_gemm_small(
    const float* __restrict__ A1,
    const uint16_t* __restrict__ Bh, const uint16_t* __restrict__ Bl,
    const float* __restrict__ al, const float* __restrict__ ar,
    float* __restrict__ el, float* __restrict__ er,
    float* __restrict__ C, int M)
{
    constexpr int ROWB = K * 2;
    constexpr int NG   = K / 8;
    constexpr int WN   = BN / 2;
    constexpr int NT   = WN / 8;
    constexpr int KS   = K / 16;

    extern __shared__ char smem[];
    const uint32_t sAH = smem_u32(smem);
    const uint32_t sAL = sAH + 128 * ROWB;
    const uint32_t sBH = sAL + 128 * ROWB;
    const uint32_t sBL = sBH + BN * ROWB;

    const int t    = threadIdx.x;
    const int wid  = t >> 5;
    const int lane = t & 31;
    const int bm   = blockIdx.x * 128;

    for (int idx = t; idx < BN * NG; idx += 256) {
        int rn = idx / NG, g = idx - rn * NG, k0 = g * 8;
        cpasync16(sBH + swz(rn, g, ROWB), Bh + (size_t)rn * K + k0);
        cpasync16(sBL + swz(rn, g, ROWB), Bl + (size_t)rn * K + k0);
    }
    for (int idx = t; idx < 128 * NG; idx += 256) {
        int row = idx / NG, g = idx - row * NG, k0 = g * 8;
        int grow = bm + row;
        float v[8] = {0, 0, 0, 0, 0, 0, 0, 0};
        if (grow < M) {
            const float* p = A1 + (size_t)grow * K + k0;
            *(float4*)&v[0] = ((const float4*)p)[0];
            *(float4*)&v[4] = ((const float4*)p)[1];
        }
        uint4 h4, l4;
        split8(v, h4, l4);
        uint32_t o = swz(row, g, ROWB);
        *(uint4*)(smem + o) = h4;
        *(uint4*)(smem + 128 * ROWB + o) = l4;
    }
    cpasync_wait();
    __syncthreads();

    const int wm = wid & 3;
    const int wn = wid >> 2;
    const int lr   = lane & 7;
    const int sel  = lane >> 3;
    const int selb1 = sel & 1;
    const int selb2 = sel >> 1;
    const int rowA_base = wm * 32 + lr + selb1 * 8;
    const int rowB_base = wn * WN + lr + selb2 * 8;

    float acc[2][NT][4];
#pragma unroll
    for (int mt = 0; mt < 2; mt++)
#pragma unroll
        for (int nt = 0; nt < NT; nt++)
#pragma unroll
            for (int q = 0; q < 4; q++) acc[mt][nt][q] = 0.f;

#pragma unroll
    for (int pr = 0; pr < 3; pr++) {
        const uint32_t baseA = (pr == 2) ? sAL : sAH;
        const uint32_t baseB = (pr == 1) ? sBL : sBH;
#pragma unroll
        for (int ks = 0; ks < KS; ks++) {
            uint32_t afr[2][4];
#pragma unroll
            for (int mt = 0; mt < 2; mt++)
                ldsm_x4(afr[mt], baseA + swz(rowA_base + mt * 16, ks * 2 + selb2, ROWB));
            uint32_t bfr[NT][2];
#pragma unroll
            for (int nt2 = 0; nt2 < NT / 2; nt2++) {
                uint32_t r[4];
                ldsm_x4(r, baseB + swz(rowB_base + nt2 * 16, ks * 2 + selb1, ROWB));
                bfr[2 * nt2][0]     = r[0];
                bfr[2 * nt2][1]     = r[1];
                bfr[2 * nt2 + 1][0] = r[2];
                bfr[2 * nt2 + 1][1] = r[3];
            }
#pragma unroll
            for (int mt = 0; mt < 2; mt++)
#pragma unroll
                for (int nt = 0; nt < NT; nt++)
                    mma16816(acc[mt][nt], afr[mt], bfr[nt]);
        }
    }

    const int colb = wn * WN + (lane & 3) * 2;
#pragma unroll
    for (int mt = 0; mt < 2; mt++) {
        int r0 = bm + wm * 32 + mt * 16 + (lane >> 2);
        int r1 = r0 + 8;
#pragma unroll
        for (int nt = 0; nt < NT; nt++) {
            int col = colb + nt * 8;
            if (r0 < M) *(float2*)&C[(size_t)r0 * BN + col] =
                make_float2(acc[mt][nt][0], acc[mt][nt][1]);
            if (r1 < M) *(float2*)&C[(size_t)r1 * BN + col] =
                make_float2(acc[mt][nt][2], acc[mt][nt][3]);
        }
    }

#pragma unroll
    for (int mt = 0; mt < 2; mt++) {
        float e[4];
#pragma unroll
        for (int q = 0; q < 4; q++) e[q] = 0.f;
#pragma unroll
        for (int nt = 0; nt < NT; nt++) {
            int c = colb + nt * 8;
            float a0 = al[c], a1 = al[c + 1];
            float b0 = ar[c], b1 = ar[c + 1];
            e[0] += acc[mt][nt][0] * a0 + acc[mt][nt][1] * a1;
            e[1] += acc[mt][nt][0] * b0 + acc[mt][nt][1] * b1;
            e[2] += acc[mt][nt][2] * a0 + acc[mt][nt][3] * a1;
            e[3] += acc[mt][nt][2] * b0 + acc[mt][nt][3] * b1;
        }
#pragma unroll
        for (int o = 1; o <= 2; o <<= 1)
#pragma unroll
            for (int q = 0; q < 4; q++)
                e[q] += __shfl_xor_sync(0xffffffffu, e[q], o);
        if ((lane & 3) == 0) {
            int r0 = bm + wm * 32 + mt * 16 + (lane >> 2);
            int r1 = r0 + 8;
            if (r0 < M) { el[2 * r0 + wn] = e[0]; er[2 * r0 + wn] = e[1]; }
            if (r1 < M) { el[2 * r1 + wn] = e[2]; er[2 * r1 + wn] = e[3]; }
        }
    }
}

// ---------------------------------------------------------------------------
// CSR build
// ---------------------------------------------------------------------------
__global__ void count_kernel(const int* __restrict__ dst, int e) {
    int i = blockIdx.x * blockDim.x + threadIdx.x;
    if (i < e) atomicAdd(&g_cnt[dst[i]], 1);
}

__global__ void scan_kernel(int n) {
    __shared__ int partial[1024];
    const int t = threadIdx.x;
    const int C = (n + 1023) / 1024;
    int s = 0;
    for (int j = 0; j < C; j++) {
        int idx = t * C + j;
        if (idx < n) s += g_cnt[idx];
    }
    partial[t] = s;
    __syncthreads();
    for (int ofs = 1; ofs < 1024; ofs <<= 1) {
        int v = (t >= ofs) ? partial[t - ofs] : 0;
        __syncthreads();
        partial[t] += v;
        __syncthreads();
    }
    int run = (t == 0) ? 0 : partial[t - 1];
    for (int j = 0; j < C; j++) {
        int idx = t * C + j;
        if (idx < n) {
            g_off[idx] = run;
            run += g_cnt[idx];
            g_cnt[idx] = 0;
        }
    }
    if (t == 1023) g_off[n] = run;
}

__global__ void fill_kernel(const int* __restrict__ src, const int* __restrict__ dst, int e) {
    int i = blockIdx.x * blockDim.x + threadIdx.x;
    if (i < e) {
        int d = dst[i];
        int p = atomicAdd(&g_cnt[d], 1);
        g_esrc[g_off[d] + p] = src[i];
    }
}

// ---------------------------------------------------------------------------
// Aggregation: warp per dst node in [node0, node0+cnt); single-pass online
// softmax with warp-deduplicated exponentials (one MUFU issue per 4-edge
// batch: lane L<16 computes exp(arg[L]), results shfl-broadcast).
// ---------------------------------------------------------------------------
__device__ __forceinline__ float leaky02(float x) { return x > 0.f ? x : 0.2f * x; }
__device__ __forceinline__ float sel4(int j, float a, float b, float c, float d) {
    return (j == 0) ? a : (j == 1) ? b : (j == 2) ? c : d;
}

template <int HD, int ACT, bool HEADMEAN>
__global__ void agg_kernel(const float* __restrict__ h,
                           const float* __restrict__ res,
                           const float* __restrict__ elp,
                           const float* __restrict__ erp,
                           float* __restrict__ out, int node0, int cnt)
{
    constexpr int V = HD / 32;
    int node = node0 + ((blockIdx.x * blockDim.x + threadIdx.x) >> 5);
    int lane = threadIdx.x & 31;
    if (node >= node0 + cnt) return;

    const int beg = g_off[node];
    const int end = g_off[node + 1];
    const float2 erv = ((const float2*)erp)[node];
    const float2* __restrict__ el2 = (const float2*)elp;
    const int* __restrict__ esrc = g_esrc;

    const bool head0 = (lane * V) < (HD / 2);
    const int j4   = lane & 3;
    const int kind = (lane >> 2) & 3;
    float m0 = -1e30f, m1 = -1e30f;
    float d0 = 0.f, d1 = 0.f;
    float acc[V];
#pragma unroll
    for (int q = 0; q < V; q++) acc[q] = 0.f;

    int i = beg;
    for (; i + 4 <= end; i += 4) {
        int s[4];
#pragma unroll
        for (int j = 0; j < 4; j++) s[j] = esrc[i + j];
        float2 ev[4];
#pragma unroll
        for (int j = 0; j < 4; j++) ev[j] = el2[s[j]];
        float hv[4][V];
#pragma unroll
        for (int j = 0; j < 4; j++) {
            if (V == 4) *(float4*)hv[j] = *(const float4*)(h + (size_t)s[j] * HD + lane * V);
            else        *(float2*)hv[j] = *(const float2*)(h + (size_t)s[j] * HD + lane * V);
        }
        // ---- all lanes compute the 16 exp ARGS (ALU only) ----
        float argA[4], argB[4], argC[4], argD[4];   // sc0, w0, sc1, w1 args
        float pm0 = m0, pm1 = m1;
#pragma unroll
        for (int j = 0; j < 4; j++) {
            float e0 = leaky02(ev[j].x + erv.x);
            float e1 = leaky02(ev[j].y + erv.y);
            float nm0 = fmaxf(pm0, e0), nm1 = fmaxf(pm1, e1);
            argA[j] = pm0 - nm0;
            argB[j] = e0 - nm0;
            argC[j] = pm1 - nm1;
            argD[j] = e1 - nm1;
            pm0 = nm0; pm1 = nm1;
        }
        m0 = pm0; m1 = pm1;
        // ---- ONE exp instruction evaluates all 16 (lane L -> arg[L]) ----
        float aA = sel4(j4, argA[0], argA[1], argA[2], argA[3]);
        float aB = sel4(j4, argB[0], argB[1], argB[2], argB[3]);
        float aC = sel4(j4, argC[0], argC[1], argC[2], argC[3]);
        float aD = sel4(j4, argD[0], argD[1], argD[2], argD[3]);
        float myarg = sel4(kind, aA, aB, aC, aD);
        float ex = __expf(myarg);
        // ---- broadcast + accumulate ----
#pragma unroll
        for (int j = 0; j < 4; j++) {
            float sc0 = __shfl_sync(0xffffffffu, ex, j);
            float w0  = __shfl_sync(0xffffffffu, ex, 4 + j);
            float sc1 = __shfl_sync(0xffffffffu, ex, 8 + j);
            float w1  = __shfl_sync(0xffffffffu, ex, 12 + j);
            d0 = d0 * sc0 + w0;
            d1 = d1 * sc1 + w1;
            float scv = head0 ? sc0 : sc1;
            float wv  = head0 ? w0  : w1;
#pragma unroll
            for (int q = 0; q < V; q++) acc[q] = fmaf(acc[q], scv, wv * hv[j][q]);
        }
    }
    for (; i < end; i++) {
        int s = esrc[i];
        float2 ev = el2[s];
        float hv[V];
        if (V == 4) *(float4*)hv = *(const float4*)(h + (size_t)s * HD + lane * V);
        else        *(float2*)hv = *(const float2*)(h + (size_t)s * HD + lane * V);
        float e0 = leaky02(ev.x + erv.x);
        float e1 = leaky02(ev.y + erv.y);
        float nm0 = fmaxf(m0, e0), nm1 = fmaxf(m1, e1);
        float sc0 = __expf(m0 - nm0), w0 = __expf(e0 - nm0);
        float sc1 = __expf(m1 - nm1), w1 = __expf(e1 - nm1);
        d0 = d0 * sc0 + w0;
        d1 = d1 * sc1 + w1;
        m0 = nm0; m1 = nm1;
        float scv = head0 ? sc0 : sc1;
        float wv  = head0 ? w0  : w1;
#pragma unroll
        for (int q = 0; q < V; q++) acc[q] = fmaf(acc[q], scv, wv * hv[q]);
    }

    const bool has = (end > beg);
    const float inv0 = has ? 1.f / d0 : 0.f;
    const float inv1 = has ? 1.f / d1 : 0.f;
    const float invv = head0 ? inv0 : inv1;

    float rr[V];
    if (V == 4) *(float4*)rr = *(const float4*)(res + (size_t)node * HD + lane * V);
    else        *(float2*)rr = *(const float2*)(res + (size_t)node * HD + lane * V);

    float v[V];
#pragma unroll
    for (int q = 0; q < V; q++) {
        v[q] = acc[q] * invv + rr[q];
        if (ACT == 0) v[q] = v[q] > 0.f ? v[q] : expm1f(v[q]);
        else          v[q] = tanhf(v[q]);
    }

    if (HEADMEAN) {
        float p[V];
#pragma unroll
        for (int q = 0; q < V; q++) p[q] = __shfl_xor_sync(0xffffffffu, v[q], 16);
        if (lane < 16) {
            float o[V];
#pragma unroll
            for (int q = 0; q < V; q++) o[q] = 0.5f * (v[q] + p[q]);
            if (V == 4) *(float4*)(out + (size_t)node * 64 + lane * V) = *(float4*)o;
            else        *(float2*)(out + (size_t)node * 64 + lane * V) = *(float2*)o;
        }
    } else {
        if (V == 4) *(float4*)(out + (size_t)node * HD + lane * V) = *(float4*)v;
        else        *(float2*)(out + (size_t)node * HD + lane * V) = *(float2*)v;
    }
}

// ---------------------------------------------------------------------------
// Launch — 3-chunk agg→gemm pipeline per boundary, ping-pong buffers (R14 DAG).
// ---------------------------------------------------------------------------
extern "C" void kernel_launch(void* const* d_in, const int* in_sizes, int n_in,
                              void* d_out, int out_size)
{
    const float* fvs = (const float*)d_in[0];
    const float* pos = (const float*)d_in[1];
    const int*   src = (const int*)d_in[2];
    const int*   dst = (const int*)d_in[3];
    const float* g0W  = (const float*)d_in[4];
    const float* g0al = (const float*)d_in[5];
    const float* g0ar = (const float*)d_in[6];
    const float* g0rW = (const float*)d_in[7];
    const float* g1W  = (const float*)d_in[8];
    const float* g1al = (const float*)d_in[9];
    const float* g1ar = (const float*)d_in[10];
    const float* g1rW = (const float*)d_in[11];
    const float* g2W  = (const float*)d_in[12];
    const float* g2al = (const float*)d_in[13];
    const float* g2ar = (const float*)d_in[14];
    const float* g2rW = (const float*)d_in[15];
    const float* p0W  = (const float*)d_in[16];
    const float* p0al = (const float*)d_in[17];
    const float* p0ar = (const float*)d_in[18];
    const float* p1W  = (const float*)d_in[19];
    const float* p1al = (const float*)d_in[20];
    const float* p1ar = (const float*)d_in[21];

    const int n = in_sizes[0] / 128;
    const int e = in_sizes[2];

    float *hb, *rhb, *elb, *erb, *hs, *hs2, *hp, *hq, *el2, *er2;
    int* cnt;
    uint16_t *wthi, *wtlo;
    cudaGetSymbolAddress((void**)&hb,   g_h);
    cudaGetSymbolAddress((void**)&rhb,  g_rh);
    cudaGetSymbolAddress((void**)&elb,  g_el);
    cudaGetSymbolAddress((void**)&erb,  g_er);
    cudaGetSymbolAddress((void**)&hs,   g_hs);
    cudaGetSymbolAddress((void**)&hs2,  g_hs2);
    cudaGetSymbolAddress((void**)&hp,   g_hp);
    cudaGetSymbolAddress((void**)&hq,   g_hq);
    cudaGetSymbolAddress((void**)&el2,  g_el2);
    cudaGetSymbolAddress((void**)&er2,  g_er2);
    cudaGetSymbolAddress((void**)&cnt,  g_cnt);
    cudaGetSymbolAddress((void**)&wthi, g_wthi);
    cudaGetSymbolAddress((void**)&wtlo, g_wtlo);

    float* h0  = hb;                       float* h1  = hb  + (size_t)NMAX * 128;
    float* rh0 = rhb;                      float* rh1 = rhb + (size_t)NMAX * 128;
    float* el0 = elb;                      float* el1 = elb + (size_t)NMAX * 2;
    float* er0 = erb;                      float* er1 = erb + (size_t)NMAX * 2;

    float* out_hs = (float*)d_out;
    float* out_hp = (float*)d_out + (size_t)n * 64;

    const int EB = (e + 255) / 256;
    const int GB = (n + 127) / 128;
    const int WB = (n + 7) / 8;

    const int CH = ((n / 3 + 127) / 128) * 128;
    int c0[3], cc[3];
    c0[0] = 0;      cc[0] = CH;
    c0[1] = CH;     cc[1] = CH;
    c0[2] = 2 * CH; cc[2] = n - 2 * CH;

    constexpr int SMEM_F     = 2 * 128 * 384 + 256 * 384;
    constexpr int SMEM_SMALL = (128 + 128 + 64 + 64) * 64 * 2;
    cudaFuncSetAttribute(tc_gemm_fused<192>,    cudaFuncAttributeMaxDynamicSharedMemorySize, SMEM_F);
    cudaFuncSetAttribute(tc_gemm_small<64, 64>, cudaFuncAttributeMaxDynamicSharedMemorySize, SMEM_SMALL);

    static cudaStream_t s1 = nullptr, s2 = nullptr, s3 = nullptr;
    static cudaEvent_t evFork, evPrep, evCSR, evP0, evP1, evG0, evG1;
    static cudaEvent_t evA0[3], evA1[3], evEnd1, evEnd2;
    if (s1 == nullptr) {
        cudaStreamCreateWithFlags(&s1, cudaStreamNonBlocking);
        cudaStreamCreateWithFlags(&s2, cudaStreamNonBlocking);
        cudaStreamCreateWithFlags(&s3, cudaStreamNonBlocking);
        cudaEventCreateWithFlags(&evFork, cudaEventDisableTiming);
        cudaEventCreateWithFlags(&evPrep, cudaEventDisableTiming);
        cudaEventCreateWithFlags(&evCSR,  cudaEventDisableTiming);
        cudaEventCreateWithFlags(&evP0,   cudaEventDisableTiming);
        cudaEventCreateWithFlags(&evP1,   cudaEventDisableTiming);
        cudaEventCreateWithFlags(&evG0,   cudaEventDisableTiming);
        cudaEventCreateWithFlags(&evG1,   cudaEventDisableTiming);
        for (int i = 0; i < 3; i++) {
            cudaEventCreateWithFlags(&evA0[i], cudaEventDisableTiming);
            cudaEventCreateWithFlags(&evA1[i], cudaEventDisableTiming);
        }
        cudaEventCreateWithFlags(&evEnd1, cudaEventDisableTiming);
        cudaEventCreateWithFlags(&evEnd2, cudaEventDisableTiming);
    }

    Prep8 pa;
    const float* Ws[8] = {g0W, g0rW, g1W, g1rW, g2W, g2rW, p0W, p1W};
    for (int m = 0; m < 8; m++) {
        pa.W[m] = Ws[m];
        pa.K[m] = (m < 6) ? 192 : 64;
        pa.N[m] = (m < 6) ? 128 : 64;
        pa.off[m] = (m < 6) ? (m >> 1) * WT_FUSED + (m & 1) * (128 * 192)
                            : 3 * WT_FUSED + (m - 6) * WT_SMALL;
    }

    const int F0 = 0 * WT_FUSED, F1 = 1 * WT_FUSED, F2 = 2 * WT_FUSED;
    const int P0 = 3 * WT_FUSED, P1 = 3 * WT_FUSED + WT_SMALL;

    // ---- fork ----
    cudaEventRecord(evFork, 0);
    cudaStreamWaitEvent(s1, evFork, 0);
    cudaStreamWaitEvent(s2, evFork, 0);
    cudaStreamWaitEvent(s3, evFork, 0);

    prep_kernel<<<64, 256, 0, s1>>>(pa);
    cudaEventRecord(evPrep, s1);
    cudaStreamWaitEvent(s2, evPrep, 0);

    // s0: CSR build (hidden under prep + gemmF0)
    cudaMemsetAsync(cnt, 0, (size_t)n * sizeof(int), 0);
    count_kernel<<<EB, 256, 0, 0>>>(dst, e);
    scan_kernel<<<1, 1024, 0, 0>>>(n);
    fill_kernel<<<EB, 256, 0, 0>>>(src, dst, e);
    cudaEventRecord(evCSR, 0);

    // ---- layer 0 GEMMs (write buffer 0) ----
    tc_gemm_fused<192><<<GB, 256, SMEM_F, s1>>>(fvs, 128, pos, wthi + F0, wtlo + F0,
                                                g0al, g0ar, el0, er0, h0, rh0, n, 0);
    cudaEventRecord(evG0, s1);
    tc_gemm_small<64, 64><<<GB, 256, SMEM_SMALL, s2>>>(pos, wthi + P0, wtlo + P0,
                                                       p0al, p0ar, el2, er2, hq, n);
    cudaStreamWaitEvent(s2, evCSR, 0);
    agg_kernel<64, 1, false><<<WB, 256, 0, s2>>>(hq, pos, el2, er2, hp, 0, n);
    cudaEventRecord(evP0, s2);

    // ---- boundary 0: agg0 chunks on s3, gemmF1 chunks trail on s1 ----
    cudaStreamWaitEvent(s3, evCSR, 0);
    cudaStreamWaitEvent(s3, evG0, 0);
    for (int i = 0; i < 3; i++) {
        agg_kernel<128, 0, false><<<(cc[i] + 7) / 8, 256, 0, s3>>>(
            h0, rh0, el0, er0, hs, c0[i], cc[i]);
        cudaEventRecord(evA0[i], s3);
    }
    cudaStreamWaitEvent(s1, evP0, 0);
    for (int i = 0; i < 3; i++) {
        cudaStreamWaitEvent(s1, evA0[i], 0);
        tc_gemm_fused<192><<<(cc[i] + 127) / 128, 256, SMEM_F, s1>>>(
            hs, 128, hp, wthi + F1, wtlo + F1,
            g1al, g1ar, el1, er1, h1, rh1, n, c0[i]);
    }
    cudaEventRecord(evG1, s1);

    // pg layer 1 (s2, overlaps boundary 0)
    tc_gemm_small<64, 64><<<GB, 256, SMEM_SMALL, s2>>>(hp, wthi + P1, wtlo + P1,
                                                       p1al, p1ar, el2, er2, hq, n);
    agg_kernel<64, 1, false><<<WB, 256, 0, s2>>>(hq, hp, el2, er2, out_hp, 0, n);
    cudaEventRecord(evP1, s2);

    // ---- boundary 1: agg1 chunks (read buf1, need ALL gemmF1 chunks) ----
    cudaStreamWaitEvent(s3, evG1, 0);
    for (int i = 0; i < 3; i++) {
        agg_kernel<128, 0, false><<<(cc[i] + 7) / 8, 256, 0, s3>>>(
            h1, rh1, el1, er1, hs2, c0[i], cc[i]);
        cudaEventRecord(evA1[i], s3);
    }
    cudaStreamWaitEvent(s1, evP1, 0);
    for (int i = 0; i < 3; i++) {
        cudaStreamWaitEvent(s1, evA1[i], 0);
        tc_gemm_fused<192><<<(cc[i] + 127) / 128, 256, SMEM_F, s1>>>(
            hs2, 128, out_hp, wthi + F2, wtlo + F2,
            g2al, g2ar, el0, er0, h0, rh0, n, c0[i]);
    }

    // ---- final agg (headmean; needs all gemmF2 chunks — stream order on s1) ----
    agg_kernel<128, 0, true><<<WB, 256, 0, s1>>>(h0, rh0, el0, er0, out_hs, 0, n);
    cudaEventRecord(evEnd1, s1);
    cudaEventRecord(evEnd2, s2);

    // ---- join ----
    cudaStreamWaitEvent(0, evEnd1, 0);
    cudaStreamWaitEvent(0, evEnd2, 0);
}